// round 1
// baseline (speedup 1.0000x reference)
#include <cuda_runtime.h>
#include <math.h>
#include <stdint.h>

// Problem constants
#define NNODES 32768
#define FDIM   215
#define HDIM   256
#define TTYPES 8
#define LLAYERS 3
#define NEDGES 524288
#define KCAT   (TTYPES * HDIM + TTYPES)   // 2056: [S | cnt]
#define BGRAPH 32
#define MAXN_  1024

// ---------------- device scratch (static: no runtime allocation) -------------
__device__ float g_h0[NNODES * HDIM];
__device__ float g_h1[NNODES * HDIM];
__device__ float g_m [NNODES * HDIM];
__device__ float g_gi[NNODES * 3 * HDIM];
__device__ float g_gh[NNODES * 3 * HDIM];
__device__ float g_S [NNODES * KCAT];          // 269.5 MB
__device__ float g_WpT [FDIM * HDIM];
__device__ float g_Wcat[KCAT * HDIM];
__device__ float g_WihT[HDIM * 3 * HDIM];
__device__ float g_WhhT[HDIM * 3 * HDIM];
__device__ int   g_deg[NNODES];
__device__ int   g_rowstart[NNODES + 1];
__device__ int   g_cursor[NNODES];
__device__ int   g_eid[NEDGES];

// ---------------- CSR build --------------------------------------------------
__global__ void hist_kernel(const int* __restrict__ dst, int* __restrict__ deg) {
    int e = blockIdx.x * 256 + threadIdx.x;
    if (e < NEDGES) atomicAdd(&deg[dst[e]], 1);
}

__global__ void scan_kernel(const int* __restrict__ deg,
                            int* __restrict__ rowstart,
                            int* __restrict__ cursor) {
    __shared__ int part[1024];
    int tid = threadIdx.x;
    int base = tid * 32;
    int local[32];
    int s = 0;
#pragma unroll
    for (int i = 0; i < 32; i++) { local[i] = s; s += deg[base + i]; }
    part[tid] = s;
    __syncthreads();
    for (int off = 1; off < 1024; off <<= 1) {
        int v = (tid >= off) ? part[tid - off] : 0;
        __syncthreads();
        part[tid] += v;
        __syncthreads();
    }
    int prev = (tid > 0) ? part[tid - 1] : 0;
#pragma unroll
    for (int i = 0; i < 32; i++) {
        int val = prev + local[i];
        rowstart[base + i] = val;
        cursor[base + i] = val;
    }
    if (tid == 1023) rowstart[NNODES] = part[1023];
}

__global__ void scatter_kernel(const int* __restrict__ dst,
                               int* __restrict__ cursor,
                               int* __restrict__ eid) {
    int e = blockIdx.x * 256 + threadIdx.x;
    if (e < NEDGES) {
        int pos = atomicAdd(&cursor[dst[e]], 1);
        eid[pos] = e;
    }
}

// ---------------- weight prep ------------------------------------------------
// out[c*R + r] = in[r*C + c]   (in: R x C)
__global__ void transpose_kernel(const float* __restrict__ in, float* __restrict__ out,
                                 int R, int C) {
    int idx = blockIdx.x * 256 + threadIdx.x;
    if (idx < R * C) {
        int r = idx / C, c = idx % C;
        out[(size_t)c * R + r] = in[idx];
    }
}

// Wcat[(t*H+d)*H + e] = Wm[t,e,d];  Wcat[(T*H+t)*H + e] = bm[t,e]
__global__ void prep_wcat_kernel(const float* __restrict__ Wm_l,
                                 const float* __restrict__ bm_l,
                                 float* __restrict__ out) {
    int idx = blockIdx.x * 256 + threadIdx.x;
    if (idx >= KCAT * HDIM) return;
    int k = idx / HDIM, e = idx % HDIM;
    float v;
    if (k < TTYPES * HDIM) {
        int t = k >> 8, d = k & 255;
        v = Wm_l[((size_t)t * HDIM + e) * HDIM + d];
    } else {
        int t = k - TTYPES * HDIM;
        v = bm_l[t * HDIM + e];
    }
    out[idx] = v;
}

// ---------------- edge aggregation: S[v, t, :] = sum h[src], + counts --------
__global__ __launch_bounds__(256) void aggregate_kernel(
    const float* __restrict__ h, const int* __restrict__ eid,
    const int* __restrict__ rowstart,
    const int* __restrict__ esrc, const int* __restrict__ etype,
    float* __restrict__ S)
{
    const int v = blockIdx.x;
    const int tid = threadIdx.x;
    __shared__ float sacc[TTYPES * HDIM];
    __shared__ int s_eid[256];
    __shared__ int s_src[256];
    __shared__ int s_typ[256];
#pragma unroll
    for (int t = 0; t < TTYPES; t++) sacc[t * HDIM + tid] = 0.f;
    int cnt = 0;   // valid for tid < TTYPES
    int start = rowstart[v], end = rowstart[v + 1];
    for (int base = start; base < end; base += 256) {
        int n = min(256, end - base);
        if (tid < n) s_eid[tid] = eid[base + tid];
        __syncthreads();
        // sort edge ids -> deterministic FP accumulation order
        if (tid == 0 && n > 1) {
            for (int i = 1; i < n; i++) {
                int key = s_eid[i]; int j = i - 1;
                while (j >= 0 && s_eid[j] > key) { s_eid[j + 1] = s_eid[j]; j--; }
                s_eid[j + 1] = key;
            }
        }
        __syncthreads();
        if (tid < n) { int e = s_eid[tid]; s_src[tid] = esrc[e]; s_typ[tid] = etype[e]; }
        __syncthreads();
        for (int j = 0; j < n; j++) {
            int t = s_typ[j]; int sidx = s_typ[j] >= 0 ? s_src[j] : 0;
            sacc[t * HDIM + tid] += __ldg(&h[(size_t)sidx * HDIM + tid]);
        }
        if (tid < TTYPES) {
            for (int j = 0; j < n; j++) cnt += (s_typ[j] == tid);
        }
        __syncthreads();
    }
    float* Sv = S + (size_t)v * KCAT;
#pragma unroll
    for (int t = 0; t < TTYPES; t++) Sv[t * HDIM + tid] = sacc[t * HDIM + tid];
    if (tid < TTYPES) Sv[TTYPES * HDIM + tid] = (float)cnt;
}

// ---------------- GEMM: C(MxN) = A(MxK) @ B(KxN) + bias[n] -------------------
// M, N multiples of 128; K arbitrary. 128x128 tile, BK=8, 256 threads, 8x8/thread.
__global__ __launch_bounds__(256) void gemm_bias_kernel(
    const float* __restrict__ A, const float* __restrict__ B,
    const float* __restrict__ bias, float* __restrict__ C,
    int M, int N, int K)
{
    __shared__ float As[8][128];
    __shared__ float Bs[8][128];
    const int bc = blockIdx.x;
    const int br = blockIdx.y;
    const int tid = threadIdx.x;
    const int tr = tid >> 4;            // 0..15
    const int tc = tid & 15;            // 0..15
    const int rowA = tid >> 1;          // 0..127
    const int colA = (tid & 1) * 4;     // 0 or 4
    const int rowB = tid >> 5;          // 0..7
    const int colB = (tid & 31) * 4;    // 0..124

    const float* Ab = A + (size_t)br * 128 * K;
    const float* Bb = B + (size_t)bc * 128;

    float acc[8][8];
#pragma unroll
    for (int i = 0; i < 8; i++)
#pragma unroll
        for (int j = 0; j < 8; j++) acc[i][j] = 0.f;

    for (int k0 = 0; k0 < K; k0 += 8) {
#pragma unroll
        for (int j = 0; j < 4; j++) {
            int k = k0 + colA + j;
            As[colA + j][rowA] = (k < K) ? Ab[(size_t)rowA * K + k] : 0.f;
        }
        {
            int k = k0 + rowB;
            float4 bv = make_float4(0.f, 0.f, 0.f, 0.f);
            if (k < K) bv = *reinterpret_cast<const float4*>(Bb + (size_t)k * N + colB);
            *reinterpret_cast<float4*>(&Bs[rowB][colB]) = bv;
        }
        __syncthreads();
#pragma unroll
        for (int kk = 0; kk < 8; kk++) {
            float ra[8], rb[8];
#pragma unroll
            for (int i = 0; i < 8; i++) ra[i] = As[kk][tr * 8 + i];
#pragma unroll
            for (int j = 0; j < 8; j++) rb[j] = Bs[kk][tc * 8 + j];
#pragma unroll
            for (int i = 0; i < 8; i++)
#pragma unroll
                for (int j = 0; j < 8; j++) acc[i][j] += ra[i] * rb[j];
        }
        __syncthreads();
    }

#pragma unroll
    for (int i = 0; i < 8; i++) {
        int row = br * 128 + tr * 8 + i;
#pragma unroll
        for (int j = 0; j < 8; j++) {
            int col = bc * 128 + tc * 8 + j;
            float b = bias ? bias[col] : 0.f;
            C[(size_t)row * N + col] = acc[i][j] + b;
        }
    }
}

// ---------------- GRU elementwise -------------------------------------------
__global__ void gru_kernel(const float* __restrict__ gi, const float* __restrict__ gh,
                           const float* __restrict__ h, float* __restrict__ hout) {
    int idx = blockIdx.x * 256 + threadIdx.x;    // NNODES*HDIM total
    int n = idx >> 8;
    int d = idx & 255;
    const float* gin = gi + (size_t)n * 3 * HDIM;
    const float* ghn = gh + (size_t)n * 3 * HDIM;
    float ir = gin[d],            hr = ghn[d];
    float iz = gin[HDIM + d],     hz = ghn[HDIM + d];
    float inn = gin[2 * HDIM + d], hn = ghn[2 * HDIM + d];
    float r = 1.f / (1.f + expf(-(ir + hr)));
    float z = 1.f / (1.f + expf(-(iz + hz)));
    float nn = tanhf(inn + r * hn);
    float hv = h[(size_t)n * HDIM + d];
    hout[(size_t)n * HDIM + d] = (1.f - z) * nn + z * hv;
}

// ---------------- readout: out[b, :] = sum over 1024 nodes -------------------
__global__ void readout_kernel(const float* __restrict__ h, float* __restrict__ out) {
    int b = blockIdx.x;
    int d = threadIdx.x;
    const float* p = h + (size_t)b * MAXN_ * HDIM + d;
    float s = 0.f;
    for (int i = 0; i < MAXN_; i++) s += p[(size_t)i * HDIM];
    out[b * HDIM + d] = s;
}

// ---------------- host orchestration ----------------------------------------
extern "C" void kernel_launch(void* const* d_in, const int* in_sizes, int n_in,
                              void* d_out, int out_size) {
    const float* node_features = (const float*)d_in[0];
    const int*   edge_index    = (const int*)  d_in[1];
    const int*   edge_type     = (const int*)  d_in[2];
    const float* Wp  = (const float*)d_in[3];
    const float* bp  = (const float*)d_in[4];
    const float* Wm  = (const float*)d_in[5];
    const float* bm  = (const float*)d_in[6];
    const float* Wih = (const float*)d_in[7];
    const float* Whh = (const float*)d_in[8];
    const float* bih = (const float*)d_in[9];
    const float* bhh = (const float*)d_in[10];
    float* out = (float*)d_out;

    const int* esrc = edge_index;
    const int* edst = edge_index + NEDGES;

    float *h0, *h1, *m, *gi, *gh, *S, *WpT, *Wcat, *WihT, *WhhT;
    int *deg, *rowstart, *cursor, *eid;
    cudaGetSymbolAddress((void**)&h0,   g_h0);
    cudaGetSymbolAddress((void**)&h1,   g_h1);
    cudaGetSymbolAddress((void**)&m,    g_m);
    cudaGetSymbolAddress((void**)&gi,   g_gi);
    cudaGetSymbolAddress((void**)&gh,   g_gh);
    cudaGetSymbolAddress((void**)&S,    g_S);
    cudaGetSymbolAddress((void**)&WpT,  g_WpT);
    cudaGetSymbolAddress((void**)&Wcat, g_Wcat);
    cudaGetSymbolAddress((void**)&WihT, g_WihT);
    cudaGetSymbolAddress((void**)&WhhT, g_WhhT);
    cudaGetSymbolAddress((void**)&deg,      g_deg);
    cudaGetSymbolAddress((void**)&rowstart, g_rowstart);
    cudaGetSymbolAddress((void**)&cursor,   g_cursor);
    cudaGetSymbolAddress((void**)&eid,      g_eid);

    // CSR by dst (built once per launch, reused for all 3 layers)
    cudaMemsetAsync(deg, 0, NNODES * sizeof(int));
    hist_kernel<<<NEDGES / 256, 256>>>(edst, deg);
    scan_kernel<<<1, 1024>>>(deg, rowstart, cursor);
    scatter_kernel<<<NEDGES / 256, 256>>>(edst, cursor, eid);

    // input projection: h0 = X @ Wp^T + bp
    transpose_kernel<<<(HDIM * FDIM + 255) / 256, 256>>>(Wp, WpT, HDIM, FDIM);
    gemm_bias_kernel<<<dim3(HDIM / 128, NNODES / 128), 256>>>(
        node_features, WpT, bp, h0, NNODES, HDIM, FDIM);

    float* hc = h0;
    float* hn = h1;
    for (int l = 0; l < LLAYERS; l++) {
        prep_wcat_kernel<<<(KCAT * HDIM) / 256, 256>>>(
            Wm + (size_t)l * TTYPES * HDIM * HDIM,
            bm + (size_t)l * TTYPES * HDIM, Wcat);
        aggregate_kernel<<<NNODES, 256>>>(hc, eid, rowstart, esrc, edge_type, S);
        gemm_bias_kernel<<<dim3(HDIM / 128, NNODES / 128), 256>>>(
            S, Wcat, (const float*)nullptr, m, NNODES, HDIM, KCAT);

        transpose_kernel<<<(3 * HDIM * HDIM + 255) / 256, 256>>>(
            Wih + (size_t)l * 3 * HDIM * HDIM, WihT, 3 * HDIM, HDIM);
        transpose_kernel<<<(3 * HDIM * HDIM + 255) / 256, 256>>>(
            Whh + (size_t)l * 3 * HDIM * HDIM, WhhT, 3 * HDIM, HDIM);

        gemm_bias_kernel<<<dim3(3 * HDIM / 128, NNODES / 128), 256>>>(
            m, WihT, bih + (size_t)l * 3 * HDIM, gi, NNODES, 3 * HDIM, HDIM);
        gemm_bias_kernel<<<dim3(3 * HDIM / 128, NNODES / 128), 256>>>(
            hc, WhhT, bhh + (size_t)l * 3 * HDIM, gh, NNODES, 3 * HDIM, HDIM);

        gru_kernel<<<(NNODES * HDIM) / 256, 256>>>(gi, gh, hc, hn);
        float* tmp = hc; hc = hn; hn = tmp;
    }

    readout_kernel<<<BGRAPH, HDIM>>>(hc, out);
}

// round 4
// speedup vs baseline: 3.1744x; 3.1744x over previous
#include <cuda_runtime.h>
#include <math.h>
#include <stdint.h>

// ---------------- problem constants ------------------------------------------
#define NNODES 32768
#define FDIM   215
#define FPAD   224            // 215 padded to 32
#define HDIM   256
#define TTYPES 8
#define LLAYERS 3
#define NEDGES 524288
#define KMSG   2080           // 8*256 + 8 counts, padded to 32
#define BGRAPH 32
#define MAXN_  1024

// ---------------- cp.async helpers -------------------------------------------
#define CP_ASYNC16(saddr, gptr) \
    asm volatile("cp.async.cg.shared.global [%0], [%1], 16;" :: "r"(saddr), "l"(gptr))
#define CP_COMMIT() asm volatile("cp.async.commit_group;" ::: "memory")
#define CP_WAIT1()  asm volatile("cp.async.wait_group 1;" ::: "memory")
#define CP_WAIT0()  asm volatile("cp.async.wait_group 0;" ::: "memory")

__device__ __forceinline__ uint32_t smem_u32(const void* p) {
    uint32_t a;
    asm("{ .reg .u64 t; cvta.to.shared.u64 t, %1; cvt.u32.u64 %0, t; }" : "=r"(a) : "l"(p));
    return a;
}
__device__ __forceinline__ uint32_t f2tf32(float f) {
    uint32_t r;
    asm("cvt.rna.tf32.f32 %0, %1;" : "=r"(r) : "f"(f));
    return r;
}
__device__ __forceinline__ void mma_tf32(float* d, const uint32_t* a, const uint32_t* b) {
    asm volatile(
        "mma.sync.aligned.m16n8k8.row.col.f32.tf32.tf32.f32 "
        "{%0,%1,%2,%3}, {%4,%5,%6,%7}, {%8,%9}, {%0,%1,%2,%3};"
        : "+f"(d[0]), "+f"(d[1]), "+f"(d[2]), "+f"(d[3])
        : "r"(a[0]), "r"(a[1]), "r"(a[2]), "r"(a[3]), "r"(b[0]), "r"(b[1]));
}

// ---------------- device scratch ---------------------------------------------
__device__ float g_h0[NNODES * HDIM];
__device__ float g_h1[NNODES * HDIM];
__device__ float g_m [NNODES * HDIM];
__device__ float g_gi[NNODES * 3 * HDIM];
__device__ float g_gh[NNODES * 3 * HDIM];
__device__ float g_S [(size_t)NNODES * KMSG];
__device__ float g_Xp [NNODES * FPAD];
__device__ float g_Wpp[HDIM * FPAD];
__device__ float g_Wcat[HDIM * KMSG];
__device__ int   g_deg[NNODES];
__device__ int   g_rowstart[NNODES + 1];
__device__ int   g_cursor[NNODES];
__device__ int   g_eid[NEDGES];

// ---------------- CSR build --------------------------------------------------
__global__ void hist_kernel(const int* __restrict__ dst, int* __restrict__ deg) {
    int e = blockIdx.x * 256 + threadIdx.x;
    if (e < NEDGES) atomicAdd(&deg[dst[e]], 1);
}

__global__ void scan_kernel(const int* __restrict__ deg,
                            int* __restrict__ rowstart, int* __restrict__ cursor) {
    __shared__ int part[1024];
    int tid = threadIdx.x;
    int base = tid * 32;
    int local[32];
    int s = 0;
#pragma unroll
    for (int i = 0; i < 32; i++) { local[i] = s; s += deg[base + i]; }
    part[tid] = s;
    __syncthreads();
    for (int off = 1; off < 1024; off <<= 1) {
        int v = (tid >= off) ? part[tid - off] : 0;
        __syncthreads();
        part[tid] += v;
        __syncthreads();
    }
    int prev = (tid > 0) ? part[tid - 1] : 0;
#pragma unroll
    for (int i = 0; i < 32; i++) {
        int val = prev + local[i];
        rowstart[base + i] = val;
        cursor[base + i] = val;
    }
    if (tid == 1023) rowstart[NNODES] = part[1023];
}

__global__ void scatter_kernel(const int* __restrict__ dst,
                               int* __restrict__ cursor, int* __restrict__ eid) {
    int e = blockIdx.x * 256 + threadIdx.x;
    if (e < NEDGES) {
        int pos = atomicAdd(&cursor[dst[e]], 1);
        eid[pos] = e;
    }
}

// ---------------- weight/input prep ------------------------------------------
__global__ void pad_x_kernel(const float* __restrict__ X, float* __restrict__ Xp) {
    int idx = blockIdx.x * 256 + threadIdx.x;             // NNODES*FPAD
    int n = idx / FPAD, c = idx % FPAD;
    Xp[idx] = (c < FDIM) ? X[(size_t)n * FDIM + c] : 0.f;
}
__global__ void pad_wp_kernel(const float* __restrict__ Wp, float* __restrict__ Wpp) {
    int idx = blockIdx.x * 256 + threadIdx.x;             // HDIM*FPAD
    int n = idx / FPAD, c = idx % FPAD;
    Wpp[idx] = (c < FDIM) ? Wp[n * FDIM + c] : 0.f;
}
// Wcat[e, t*H+d] = Wm[t,e,d];  Wcat[e, 2048+t] = bm[t,e]; pad cols zero
__global__ void prep_wcat_kernel(const float* __restrict__ Wm_l,
                                 const float* __restrict__ bm_l, float* __restrict__ W) {
    int idx = blockIdx.x * 256 + threadIdx.x;             // HDIM*KMSG
    int e = idx / KMSG, k = idx % KMSG;
    float v = 0.f;
    if (k < TTYPES * HDIM) {
        int t = k >> 8, d = k & 255;
        v = Wm_l[((size_t)t * HDIM + e) * HDIM + d];
    } else if (k < TTYPES * HDIM + TTYPES) {
        int t = k - TTYPES * HDIM;
        v = bm_l[t * HDIM + e];
    }
    W[idx] = v;
}

// ---------------- edge aggregation -------------------------------------------
__global__ __launch_bounds__(256) void aggregate_kernel(
    const float* __restrict__ h, const int* __restrict__ eid,
    const int* __restrict__ rowstart,
    const int* __restrict__ esrc, const int* __restrict__ etype,
    float* __restrict__ S)
{
    const int v = blockIdx.x;
    const int tid = threadIdx.x;
    __shared__ float sacc[TTYPES * HDIM];
    __shared__ int s_eid[256];
    __shared__ int s_src[256];
    __shared__ int s_typ[256];
#pragma unroll
    for (int t = 0; t < TTYPES; t++) sacc[t * HDIM + tid] = 0.f;
    int cnt = 0;
    int start = rowstart[v], end = rowstart[v + 1];
    for (int base = start; base < end; base += 256) {
        int n = min(256, end - base);
        if (tid < n) s_eid[tid] = eid[base + tid];
        __syncthreads();
        if (tid == 0 && n > 1) {                       // deterministic sum order
            for (int i = 1; i < n; i++) {
                int key = s_eid[i]; int j = i - 1;
                while (j >= 0 && s_eid[j] > key) { s_eid[j + 1] = s_eid[j]; j--; }
                s_eid[j + 1] = key;
            }
        }
        __syncthreads();
        if (tid < n) { int e = s_eid[tid]; s_src[tid] = esrc[e]; s_typ[tid] = etype[e]; }
        __syncthreads();
        for (int j = 0; j < n; j++) {
            int t = s_typ[j];
            sacc[t * HDIM + tid] += __ldg(&h[(size_t)s_src[j] * HDIM + tid]);
        }
        if (tid < TTYPES) {
            for (int j = 0; j < n; j++) cnt += (s_typ[j] == tid);
        }
        __syncthreads();
    }
    float* Sv = S + (size_t)v * KMSG;
#pragma unroll
    for (int t = 0; t < TTYPES; t++) Sv[t * HDIM + tid] = sacc[t * HDIM + tid];
    if (tid < TTYPES) Sv[TTYPES * HDIM + tid] = (float)cnt;
    else if (tid < 32) Sv[TTYPES * HDIM + tid] = 0.f;   // pad cols 2056..2079
}

// ---------------- tf32 mma.sync GEMM -----------------------------------------
// C[M,N] = A(MxK, row-major) @ B(NxK, row-major)^T + bias.
// CTA tile 128x128, BK=32, 256 threads = 8 warps (4 M x 2 N), warp tile 32x64.
// Shared layout: element (r,k) at float index r*32 + (k ^ ((r&7)*4))  (conflict-free).
// Per buffer: A 16KB + B 16KB = 32KB; two buffers.
#define BUF_BYTES  32768
#define BUF_FLOATS 8192
#define GEMM_SMEM  (2 * BUF_BYTES)

__global__ __launch_bounds__(256, 2) void gemm_tf32_kernel(
    const float* __restrict__ A, const float* __restrict__ B,
    const float* __restrict__ bias, float* __restrict__ C,
    int K, int N)
{
    extern __shared__ float smf[];
    const int tid  = threadIdx.x;
    const int wid  = tid >> 5;
    const int lane = tid & 31;
    const int gid  = lane >> 2;       // 0..7
    const int tig  = lane & 3;        // 0..3
    const int wm   = wid >> 1;        // 0..3 : warp row
    const int wn   = wid & 1;         // 0..1 : warp col
    const int br   = blockIdx.x;
    const int cb   = blockIdx.y;

    const float* Arow = A + (size_t)(br * 128) * K;
    const float* Bt   = B + (size_t)(cb * 128) * K;
    const uint32_t smb = smem_u32(smf);

    const int NC = K >> 5;

    float acc[2][8][4];
#pragma unroll
    for (int mt = 0; mt < 2; mt++)
#pragma unroll
        for (int nt = 0; nt < 8; nt++)
#pragma unroll
            for (int v = 0; v < 4; v++) acc[mt][nt][v] = 0.f;

    auto load_chunk = [&](int c) {
        const int buf = c & 1;
        const int k0 = c * 32;
        uint32_t abase = smb + buf * BUF_BYTES;
        uint32_t bbase = abase + 16384;
#pragma unroll
        for (int i = 0; i < 4; i++) {
            int idx = tid + i * 256;                 // 0..1023
            int row = idx >> 3, g4 = (idx & 7) * 4;
            int sw = row * 32 + (g4 ^ ((row & 7) * 4));
            CP_ASYNC16(abase + sw * 4, Arow + (size_t)row * K + k0 + g4);
            CP_ASYNC16(bbase + sw * 4, Bt   + (size_t)row * K + k0 + g4);
        }
        CP_COMMIT();
    };

    load_chunk(0);
    for (int c = 0; c < NC; c++) {
        if (c + 1 < NC) { load_chunk(c + 1); CP_WAIT1(); }
        else            { CP_WAIT0(); }
        __syncthreads();

        const float* Asb = smf + (c & 1) * BUF_FLOATS;
        const float* Bsb = Asb + 4096;
        const int sw = gid * 4;                      // (r&7)*4 == gid*4 for our rows
#pragma unroll
        for (int ks = 0; ks < 4; ks++) {
            const int kb = ks * 8;
            const int kA = (kb + tig) ^ sw;
            const int kB = (kb + tig + 4) ^ sw;
            uint32_t afr[2][4];
#pragma unroll
            for (int mt = 0; mt < 2; mt++) {
                int r0 = wm * 32 + mt * 16 + gid;
                afr[mt][0] = f2tf32(Asb[r0 * 32 + kA]);
                afr[mt][1] = f2tf32(Asb[(r0 + 8) * 32 + kA]);
                afr[mt][2] = f2tf32(Asb[r0 * 32 + kB]);
                afr[mt][3] = f2tf32(Asb[(r0 + 8) * 32 + kB]);
            }
            uint32_t bfr[8][2];
#pragma unroll
            for (int nt = 0; nt < 8; nt++) {
                int cn = wn * 64 + nt * 8 + gid;
                bfr[nt][0] = f2tf32(Bsb[cn * 32 + kA]);
                bfr[nt][1] = f2tf32(Bsb[cn * 32 + kB]);
            }
#pragma unroll
            for (int mt = 0; mt < 2; mt++)
#pragma unroll
                for (int nt = 0; nt < 8; nt++)
                    mma_tf32(acc[mt][nt], afr[mt], bfr[nt]);
        }
        __syncthreads();
    }

    // epilogue
    const int col0 = cb * 128 + wn * 64;
#pragma unroll
    for (int mt = 0; mt < 2; mt++) {
        int r0 = br * 128 + wm * 32 + mt * 16 + gid;
#pragma unroll
        for (int nt = 0; nt < 8; nt++) {
            int col = col0 + nt * 8 + tig * 2;
            float b0 = 0.f, b1 = 0.f;
            if (bias) { b0 = __ldg(&bias[col]); b1 = __ldg(&bias[col + 1]); }
            float2 v0 = make_float2(acc[mt][nt][0] + b0, acc[mt][nt][1] + b1);
            float2 v1 = make_float2(acc[mt][nt][2] + b0, acc[mt][nt][3] + b1);
            *reinterpret_cast<float2*>(C + (size_t)r0 * N + col) = v0;
            *reinterpret_cast<float2*>(C + (size_t)(r0 + 8) * N + col) = v1;
        }
    }
}

// ---------------- GRU elementwise --------------------------------------------
__global__ void gru_kernel(const float* __restrict__ gi, const float* __restrict__ gh,
                           const float* __restrict__ h, float* __restrict__ hout) {
    int idx = blockIdx.x * 256 + threadIdx.x;
    int n = idx >> 8;
    int d = idx & 255;
    const float* gin = gi + (size_t)n * 3 * HDIM;
    const float* ghn = gh + (size_t)n * 3 * HDIM;
    float ir = gin[d],             hr = ghn[d];
    float iz = gin[HDIM + d],      hz = ghn[HDIM + d];
    float inn = gin[2 * HDIM + d], hn = ghn[2 * HDIM + d];
    float r = 1.f / (1.f + expf(-(ir + hr)));
    float z = 1.f / (1.f + expf(-(iz + hz)));
    float nn = tanhf(inn + r * hn);
    float hv = h[(size_t)n * HDIM + d];
    hout[(size_t)n * HDIM + d] = (1.f - z) * nn + z * hv;
}

// ---------------- readout ----------------------------------------------------
__global__ void readout_kernel(const float* __restrict__ h, float* __restrict__ out) {
    int b = blockIdx.x;
    int d = threadIdx.x;
    const float* p = h + (size_t)b * MAXN_ * HDIM + d;
    float s = 0.f;
    for (int i = 0; i < MAXN_; i++) s += p[(size_t)i * HDIM];
    out[b * HDIM + d] = s;
}

// ---------------- host orchestration -----------------------------------------
extern "C" void kernel_launch(void* const* d_in, const int* in_sizes, int n_in,
                              void* d_out, int out_size) {
    const float* node_features = (const float*)d_in[0];
    const int*   edge_index    = (const int*)  d_in[1];
    const int*   edge_type     = (const int*)  d_in[2];
    const float* Wp  = (const float*)d_in[3];
    const float* bp  = (const float*)d_in[4];
    const float* Wm  = (const float*)d_in[5];
    const float* bm  = (const float*)d_in[6];
    const float* Wih = (const float*)d_in[7];
    const float* Whh = (const float*)d_in[8];
    const float* bih = (const float*)d_in[9];
    const float* bhh = (const float*)d_in[10];
    float* out = (float*)d_out;

    const int* esrc = edge_index;
    const int* edst = edge_index + NEDGES;

    float *h0, *h1, *m, *gi, *gh, *S, *Xp, *Wpp, *Wcat;
    int *deg, *rowstart, *cursor, *eid;
    cudaGetSymbolAddress((void**)&h0,   g_h0);
    cudaGetSymbolAddress((void**)&h1,   g_h1);
    cudaGetSymbolAddress((void**)&m,    g_m);
    cudaGetSymbolAddress((void**)&gi,   g_gi);
    cudaGetSymbolAddress((void**)&gh,   g_gh);
    cudaGetSymbolAddress((void**)&S,    g_S);
    cudaGetSymbolAddress((void**)&Xp,   g_Xp);
    cudaGetSymbolAddress((void**)&Wpp,  g_Wpp);
    cudaGetSymbolAddress((void**)&Wcat, g_Wcat);
    cudaGetSymbolAddress((void**)&deg,      g_deg);
    cudaGetSymbolAddress((void**)&rowstart, g_rowstart);
    cudaGetSymbolAddress((void**)&cursor,   g_cursor);
    cudaGetSymbolAddress((void**)&eid,      g_eid);

    cudaFuncSetAttribute(gemm_tf32_kernel,
                         cudaFuncAttributeMaxDynamicSharedMemorySize, GEMM_SMEM);

    // CSR by dst (reused across layers)
    cudaMemsetAsync(deg, 0, NNODES * sizeof(int));
    hist_kernel<<<NEDGES / 256, 256>>>(edst, deg);
    scan_kernel<<<1, 1024>>>(deg, rowstart, cursor);
    scatter_kernel<<<NEDGES / 256, 256>>>(edst, cursor, eid);

    // padded inputs for projection GEMM
    pad_x_kernel<<<(NNODES * FPAD) / 256, 256>>>(node_features, Xp);
    pad_wp_kernel<<<(HDIM * FPAD) / 256, 256>>>(Wp, Wpp);

    // h0 = Xp @ Wpp^T + bp      (M=32768, N=256, K=224)
    gemm_tf32_kernel<<<dim3(NNODES / 128, HDIM / 128), 256, GEMM_SMEM>>>(
        Xp, Wpp, bp, h0, FPAD, HDIM);

    float* hc = h0;
    float* hn = h1;
    for (int l = 0; l < LLAYERS; l++) {
        prep_wcat_kernel<<<(HDIM * KMSG) / 256, 256>>>(
            Wm + (size_t)l * TTYPES * HDIM * HDIM,
            bm + (size_t)l * TTYPES * HDIM, Wcat);
        aggregate_kernel<<<NNODES, 256>>>(hc, eid, rowstart, esrc, edge_type, S);
        // m = S @ Wcat^T          (N=256, K=2080)
        gemm_tf32_kernel<<<dim3(NNODES / 128, HDIM / 128), 256, GEMM_SMEM>>>(
            S, Wcat, (const float*)nullptr, m, KMSG, HDIM);
        // gi = m @ Wih^T + bih ; gh = hc @ Whh^T + bhh   (N=768, K=256)
        gemm_tf32_kernel<<<dim3(NNODES / 128, 3 * HDIM / 128), 256, GEMM_SMEM>>>(
            m, Wih + (size_t)l * 3 * HDIM * HDIM, bih + (size_t)l * 3 * HDIM,
            gi, HDIM, 3 * HDIM);
        gemm_tf32_kernel<<<dim3(NNODES / 128, 3 * HDIM / 128), 256, GEMM_SMEM>>>(
            hc, Whh + (size_t)l * 3 * HDIM * HDIM, bhh + (size_t)l * 3 * HDIM,
            gh, HDIM, 3 * HDIM);

        gru_kernel<<<(NNODES * HDIM) / 256, 256>>>(gi, gh, hc, hn);
        float* tmp = hc; hc = hn; hn = tmp;
    }

    readout_kernel<<<BGRAPH, HDIM>>>(hc, out);
}

// round 5
// speedup vs baseline: 3.4242x; 1.0787x over previous
#include <cuda_runtime.h>
#include <math.h>
#include <stdint.h>

// ---------------- problem constants ------------------------------------------
#define NNODES 32768
#define FDIM   215
#define FPAD   224            // 215 padded to 32
#define HDIM   256
#define TTYPES 8
#define LLAYERS 3
#define NEDGES 524288
#define KMSG   2080           // 8*256 + 8 counts, padded to 32
#define BGRAPH 32
#define MAXN_  1024

// ---------------- cp.async helpers -------------------------------------------
#define CP_ASYNC16(saddr, gptr) \
    asm volatile("cp.async.cg.shared.global [%0], [%1], 16;" :: "r"(saddr), "l"(gptr))
#define CP_COMMIT() asm volatile("cp.async.commit_group;" ::: "memory")
#define CP_WAIT1()  asm volatile("cp.async.wait_group 1;" ::: "memory")
#define CP_WAIT0()  asm volatile("cp.async.wait_group 0;" ::: "memory")

__device__ __forceinline__ uint32_t smem_u32(const void* p) {
    uint32_t a;
    asm("{ .reg .u64 t; cvta.to.shared.u64 t, %1; cvt.u32.u64 %0, t; }" : "=r"(a) : "l"(p));
    return a;
}
__device__ __forceinline__ float f2tf32f(float f) {
    uint32_t r;
    asm("cvt.rna.tf32.f32 %0, %1;" : "=r"(r) : "f"(f));
    return __uint_as_float(r);
}
__device__ __forceinline__ void mma_tf32(float* d, const uint32_t* a, const uint32_t* b) {
    asm volatile(
        "mma.sync.aligned.m16n8k8.row.col.f32.tf32.tf32.f32 "
        "{%0,%1,%2,%3}, {%4,%5,%6,%7}, {%8,%9}, {%0,%1,%2,%3};"
        : "+f"(d[0]), "+f"(d[1]), "+f"(d[2]), "+f"(d[3])
        : "r"(a[0]), "r"(a[1]), "r"(a[2]), "r"(a[3]), "r"(b[0]), "r"(b[1]));
}

// ---------------- device scratch ---------------------------------------------
__device__ float g_h0[NNODES * HDIM];
__device__ float g_h1[NNODES * HDIM];
__device__ float g_ht[NNODES * HDIM];          // tf32 copy of current h (GEMM A)
__device__ float g_m [NNODES * HDIM];          // tf32 (written converted)
__device__ float g_gi[NNODES * 3 * HDIM];
__device__ float g_gh[NNODES * 3 * HDIM];
__device__ float g_S [(size_t)NNODES * KMSG];  // tf32 (written converted)
__device__ float g_Xp [NNODES * FPAD];         // tf32
__device__ float g_Wpp[HDIM * FPAD];           // tf32
__device__ float g_Wcat[HDIM * KMSG];          // tf32
__device__ float g_Wih_t[LLAYERS * 3 * HDIM * HDIM];  // tf32
__device__ float g_Whh_t[LLAYERS * 3 * HDIM * HDIM];  // tf32
__device__ float g_part[BGRAPH * 8 * HDIM];
__device__ int   g_deg[NNODES];
__device__ int   g_rowstart[NNODES + 1];
__device__ int   g_cursor[NNODES];
__device__ int   g_eid[NEDGES];

// ---------------- CSR build --------------------------------------------------
__global__ void hist_kernel(const int* __restrict__ dst, int* __restrict__ deg) {
    int e = blockIdx.x * 256 + threadIdx.x;
    if (e < NEDGES) atomicAdd(&deg[dst[e]], 1);
}

__global__ void scan_kernel(const int* __restrict__ deg,
                            int* __restrict__ rowstart, int* __restrict__ cursor) {
    __shared__ int part[1024];
    int tid = threadIdx.x;
    int base = tid * 32;
    int local[32];
    int s = 0;
#pragma unroll
    for (int i = 0; i < 32; i++) { local[i] = s; s += deg[base + i]; }
    part[tid] = s;
    __syncthreads();
    for (int off = 1; off < 1024; off <<= 1) {
        int v = (tid >= off) ? part[tid - off] : 0;
        __syncthreads();
        part[tid] += v;
        __syncthreads();
    }
    int prev = (tid > 0) ? part[tid - 1] : 0;
#pragma unroll
    for (int i = 0; i < 32; i++) {
        int val = prev + local[i];
        rowstart[base + i] = val;
        cursor[base + i] = val;
    }
    if (tid == 1023) rowstart[NNODES] = part[1023];
}

__global__ void scatter_kernel(const int* __restrict__ dst,
                               int* __restrict__ cursor, int* __restrict__ eid) {
    int e = blockIdx.x * 256 + threadIdx.x;
    if (e < NEDGES) {
        int pos = atomicAdd(&cursor[dst[e]], 1);
        eid[pos] = e;
    }
}

// ---------------- weight/input prep (all outputs tf32-rounded) ----------------
__global__ void pad_x_kernel(const float* __restrict__ X, float* __restrict__ Xp) {
    int idx = blockIdx.x * 256 + threadIdx.x;             // NNODES*FPAD
    int n = idx / FPAD, c = idx % FPAD;
    Xp[idx] = (c < FDIM) ? f2tf32f(X[(size_t)n * FDIM + c]) : 0.f;
}
__global__ void pad_wp_kernel(const float* __restrict__ Wp, float* __restrict__ Wpp) {
    int idx = blockIdx.x * 256 + threadIdx.x;             // HDIM*FPAD
    int n = idx / FPAD, c = idx % FPAD;
    Wpp[idx] = (c < FDIM) ? f2tf32f(Wp[n * FDIM + c]) : 0.f;
}
// Wih/Whh tf32 copies (all layers at once), each L*3H*H elements
__global__ void cvt_wg_kernel(const float* __restrict__ Wih, const float* __restrict__ Whh,
                              float* __restrict__ Wih_t, float* __restrict__ Whh_t) {
    int idx = blockIdx.x * 256 + threadIdx.x;             // L*3H*H
    Wih_t[idx] = f2tf32f(Wih[idx]);
    Whh_t[idx] = f2tf32f(Whh[idx]);
}
__global__ void cvt_h_kernel(const float* __restrict__ h, float* __restrict__ ht) {
    int idx = blockIdx.x * 256 + threadIdx.x;             // NNODES*HDIM
    ht[idx] = f2tf32f(h[idx]);
}
// Wcat[e, t*H+d] = Wm[t,e,d];  Wcat[e, 2048+t] = bm[t,e]; pad cols zero; tf32
__global__ void prep_wcat_kernel(const float* __restrict__ Wm_l,
                                 const float* __restrict__ bm_l, float* __restrict__ W) {
    int idx = blockIdx.x * 256 + threadIdx.x;             // HDIM*KMSG
    int e = idx / KMSG, k = idx % KMSG;
    float v = 0.f;
    if (k < TTYPES * HDIM) {
        int t = k >> 8, d = k & 255;
        v = Wm_l[((size_t)t * HDIM + e) * HDIM + d];
    } else if (k < TTYPES * HDIM + TTYPES) {
        int t = k - TTYPES * HDIM;
        v = bm_l[t * HDIM + e];
    }
    W[idx] = f2tf32f(v);
}

// ---------------- edge aggregation (S stored tf32-rounded) --------------------
__global__ __launch_bounds__(256) void aggregate_kernel(
    const float* __restrict__ h, const int* __restrict__ eid,
    const int* __restrict__ rowstart,
    const int* __restrict__ esrc, const int* __restrict__ etype,
    float* __restrict__ S)
{
    const int v = blockIdx.x;
    const int tid = threadIdx.x;
    __shared__ float sacc[TTYPES * HDIM];
    __shared__ int s_eid[256];
    __shared__ int s_src[256];
    __shared__ int s_typ[256];
#pragma unroll
    for (int t = 0; t < TTYPES; t++) sacc[t * HDIM + tid] = 0.f;
    int cnt = 0;
    int start = rowstart[v], end = rowstart[v + 1];
    for (int base = start; base < end; base += 256) {
        int n = min(256, end - base);
        if (tid < n) s_eid[tid] = eid[base + tid];
        __syncthreads();
        if (tid == 0 && n > 1) {                       // deterministic sum order
            for (int i = 1; i < n; i++) {
                int key = s_eid[i]; int j = i - 1;
                while (j >= 0 && s_eid[j] > key) { s_eid[j + 1] = s_eid[j]; j--; }
                s_eid[j + 1] = key;
            }
        }
        __syncthreads();
        if (tid < n) { int e = s_eid[tid]; s_src[tid] = esrc[e]; s_typ[tid] = etype[e]; }
        __syncthreads();
        for (int j = 0; j < n; j++) {
            int t = s_typ[j];
            sacc[t * HDIM + tid] += __ldg(&h[(size_t)s_src[j] * HDIM + tid]);
        }
        if (tid < TTYPES) {
            for (int j = 0; j < n; j++) cnt += (s_typ[j] == tid);
        }
        __syncthreads();
    }
    float* Sv = S + (size_t)v * KMSG;
#pragma unroll
    for (int t = 0; t < TTYPES; t++) Sv[t * HDIM + tid] = f2tf32f(sacc[t * HDIM + tid]);
    if (tid < TTYPES) Sv[TTYPES * HDIM + tid] = (float)cnt;   // exact in tf32 (< 2048)
    else if (tid < 32) Sv[TTYPES * HDIM + tid] = 0.f;         // pad cols 2056..2079
}

// ---------------- tf32 mma.sync GEMM -----------------------------------------
// C[M,N] = A(MxK, row-major, tf32 bits) @ B(NxK, row-major, tf32 bits)^T + bias.
// CTA tile 128x128, BK=32, 256 threads = 8 warps (4 M x 2 N), warp tile 32x64.
// Shared layout: element (r,k) at float index r*32 + (k ^ ((r&7)*4)).
#define BUF_BYTES  32768
#define BUF_FLOATS 8192
#define GEMM_SMEM  (2 * BUF_BYTES)

__global__ __launch_bounds__(256, 2) void gemm_tf32_kernel(
    const float* __restrict__ A, const float* __restrict__ B,
    const float* __restrict__ bias, float* __restrict__ C,
    int K, int N, int conv_out)
{
    extern __shared__ float smf[];
    const int tid  = threadIdx.x;
    const int wid  = tid >> 5;
    const int lane = tid & 31;
    const int gid  = lane >> 2;       // 0..7
    const int tig  = lane & 3;        // 0..3
    const int wm   = wid >> 1;        // 0..3 : warp row
    const int wn   = wid & 1;         // 0..1 : warp col
    const int br   = blockIdx.x;
    const int cb   = blockIdx.y;

    const float* Arow = A + (size_t)(br * 128) * K;
    const float* Bt   = B + (size_t)(cb * 128) * K;
    const uint32_t smb = smem_u32(smf);

    const int NC = K >> 5;

    float acc[2][8][4];
#pragma unroll
    for (int mt = 0; mt < 2; mt++)
#pragma unroll
        for (int nt = 0; nt < 8; nt++)
#pragma unroll
            for (int v = 0; v < 4; v++) acc[mt][nt][v] = 0.f;

    auto load_chunk = [&](int c) {
        const int buf = c & 1;
        const int k0 = c * 32;
        uint32_t abase = smb + buf * BUF_BYTES;
        uint32_t bbase = abase + 16384;
#pragma unroll
        for (int i = 0; i < 4; i++) {
            int idx = tid + i * 256;                 // 0..1023
            int row = idx >> 3, g4 = (idx & 7) * 4;
            int sw = row * 32 + (g4 ^ ((row & 7) * 4));
            CP_ASYNC16(abase + sw * 4, Arow + (size_t)row * K + k0 + g4);
            CP_ASYNC16(bbase + sw * 4, Bt   + (size_t)row * K + k0 + g4);
        }
        CP_COMMIT();
    };

    load_chunk(0);
    for (int c = 0; c < NC; c++) {
        if (c + 1 < NC) { load_chunk(c + 1); CP_WAIT1(); }
        else            { CP_WAIT0(); }
        __syncthreads();

        const float* Asb = smf + (c & 1) * BUF_FLOATS;
        const float* Bsb = Asb + 4096;
        const int sw = gid * 4;                      // (r&7)*4 == gid*4 for our rows
#pragma unroll
        for (int ks = 0; ks < 4; ks++) {
            const int kb = ks * 8;
            const int kA = (kb + tig) ^ sw;
            const int kB = (kb + tig + 4) ^ sw;
            uint32_t afr[2][4];
#pragma unroll
            for (int mt = 0; mt < 2; mt++) {
                int r0 = wm * 32 + mt * 16 + gid;
                afr[mt][0] = __float_as_uint(Asb[r0 * 32 + kA]);
                afr[mt][1] = __float_as_uint(Asb[(r0 + 8) * 32 + kA]);
                afr[mt][2] = __float_as_uint(Asb[r0 * 32 + kB]);
                afr[mt][3] = __float_as_uint(Asb[(r0 + 8) * 32 + kB]);
            }
            uint32_t bfr[8][2];
#pragma unroll
            for (int nt = 0; nt < 8; nt++) {
                int cn = wn * 64 + nt * 8 + gid;
                bfr[nt][0] = __float_as_uint(Bsb[cn * 32 + kA]);
                bfr[nt][1] = __float_as_uint(Bsb[cn * 32 + kB]);
            }
#pragma unroll
            for (int mt = 0; mt < 2; mt++)
#pragma unroll
                for (int nt = 0; nt < 8; nt++)
                    mma_tf32(acc[mt][nt], afr[mt], bfr[nt]);
        }
        __syncthreads();
    }

    // epilogue
    const int col0 = cb * 128 + wn * 64;
#pragma unroll
    for (int mt = 0; mt < 2; mt++) {
        int r0 = br * 128 + wm * 32 + mt * 16 + gid;
#pragma unroll
        for (int nt = 0; nt < 8; nt++) {
            int col = col0 + nt * 8 + tig * 2;
            float b0 = 0.f, b1 = 0.f;
            if (bias) { b0 = __ldg(&bias[col]); b1 = __ldg(&bias[col + 1]); }
            float2 v0 = make_float2(acc[mt][nt][0] + b0, acc[mt][nt][1] + b1);
            float2 v1 = make_float2(acc[mt][nt][2] + b0, acc[mt][nt][3] + b1);
            if (conv_out) {
                v0.x = f2tf32f(v0.x); v0.y = f2tf32f(v0.y);
                v1.x = f2tf32f(v1.x); v1.y = f2tf32f(v1.y);
            }
            *reinterpret_cast<float2*>(C + (size_t)r0 * N + col) = v0;
            *reinterpret_cast<float2*>(C + (size_t)(r0 + 8) * N + col) = v1;
        }
    }
}

// ---------------- GRU elementwise (float4, also emits tf32 copy) --------------
__global__ void gru_kernel(const float* __restrict__ gi, const float* __restrict__ gh,
                           const float* __restrict__ h, float* __restrict__ hout,
                           float* __restrict__ hout_t) {
    int idx = blockIdx.x * 256 + threadIdx.x;    // NNODES*HDIM/4 total
    int n = idx >> 6;
    int d4 = (idx & 63) * 4;
    const float* gin = gi + (size_t)n * 3 * HDIM;
    const float* ghn = gh + (size_t)n * 3 * HDIM;
    float4 ir = *reinterpret_cast<const float4*>(gin + d4);
    float4 iz = *reinterpret_cast<const float4*>(gin + HDIM + d4);
    float4 in_ = *reinterpret_cast<const float4*>(gin + 2 * HDIM + d4);
    float4 hr = *reinterpret_cast<const float4*>(ghn + d4);
    float4 hz = *reinterpret_cast<const float4*>(ghn + HDIM + d4);
    float4 hn_ = *reinterpret_cast<const float4*>(ghn + 2 * HDIM + d4);
    float4 hv = *reinterpret_cast<const float4*>(h + (size_t)n * HDIM + d4);
    float4 o, ot;
#define GRU1(X) do { \
        float r = 1.f / (1.f + expf(-(ir.X + hr.X))); \
        float z = 1.f / (1.f + expf(-(iz.X + hz.X))); \
        float nn = tanhf(in_.X + r * hn_.X); \
        o.X = (1.f - z) * nn + z * hv.X; \
        ot.X = f2tf32f(o.X); \
    } while (0)
    GRU1(x); GRU1(y); GRU1(z); GRU1(w);
#undef GRU1
    *reinterpret_cast<float4*>(hout + (size_t)n * HDIM + d4) = o;
    *reinterpret_cast<float4*>(hout_t + (size_t)n * HDIM + d4) = ot;
}

// ---------------- readout (two-pass, deterministic) ---------------------------
__global__ void readout_part_kernel(const float* __restrict__ h, float* __restrict__ part) {
    int b = blockIdx.x;            // 0..31
    int c = blockIdx.y;            // 0..7
    int d = threadIdx.x;           // 0..255
    const float* p = h + ((size_t)b * MAXN_ + c * 128) * HDIM + d;
    float s = 0.f;
#pragma unroll 4
    for (int i = 0; i < 128; i++) s += p[(size_t)i * HDIM];
    part[(b * 8 + c) * HDIM + d] = s;
}
__global__ void readout_reduce_kernel(const float* __restrict__ part, float* __restrict__ out) {
    int b = blockIdx.x;
    int d = threadIdx.x;
    float s = 0.f;
#pragma unroll
    for (int c = 0; c < 8; c++) s += part[(b * 8 + c) * HDIM + d];
    out[b * HDIM + d] = s;
}

// ---------------- host orchestration -----------------------------------------
extern "C" void kernel_launch(void* const* d_in, const int* in_sizes, int n_in,
                              void* d_out, int out_size) {
    const float* node_features = (const float*)d_in[0];
    const int*   edge_index    = (const int*)  d_in[1];
    const int*   edge_type     = (const int*)  d_in[2];
    const float* Wp  = (const float*)d_in[3];
    const float* bp  = (const float*)d_in[4];
    const float* Wm  = (const float*)d_in[5];
    const float* bm  = (const float*)d_in[6];
    const float* Wih = (const float*)d_in[7];
    const float* Whh = (const float*)d_in[8];
    const float* bih = (const float*)d_in[9];
    const float* bhh = (const float*)d_in[10];
    float* out = (float*)d_out;

    const int* esrc = edge_index;
    const int* edst = edge_index + NEDGES;

    float *h0, *h1, *ht, *m, *gi, *gh, *S, *Xp, *Wpp, *Wcat, *Wih_t, *Whh_t, *part;
    int *deg, *rowstart, *cursor, *eid;
    cudaGetSymbolAddress((void**)&h0,    g_h0);
    cudaGetSymbolAddress((void**)&h1,    g_h1);
    cudaGetSymbolAddress((void**)&ht,    g_ht);
    cudaGetSymbolAddress((void**)&m,     g_m);
    cudaGetSymbolAddress((void**)&gi,    g_gi);
    cudaGetSymbolAddress((void**)&gh,    g_gh);
    cudaGetSymbolAddress((void**)&S,     g_S);
    cudaGetSymbolAddress((void**)&Xp,    g_Xp);
    cudaGetSymbolAddress((void**)&Wpp,   g_Wpp);
    cudaGetSymbolAddress((void**)&Wcat,  g_Wcat);
    cudaGetSymbolAddress((void**)&Wih_t, g_Wih_t);
    cudaGetSymbolAddress((void**)&Whh_t, g_Whh_t);
    cudaGetSymbolAddress((void**)&part,  g_part);
    cudaGetSymbolAddress((void**)&deg,      g_deg);
    cudaGetSymbolAddress((void**)&rowstart, g_rowstart);
    cudaGetSymbolAddress((void**)&cursor,   g_cursor);
    cudaGetSymbolAddress((void**)&eid,      g_eid);

    cudaFuncSetAttribute(gemm_tf32_kernel,
                         cudaFuncAttributeMaxDynamicSharedMemorySize, GEMM_SMEM);

    // prep (positions chosen so stream op #5 = proj GEMM for ncu capture)
    pad_x_kernel<<<(NNODES * FPAD) / 256, 256>>>(node_features, Xp);          // 1
    pad_wp_kernel<<<(HDIM * FPAD) / 256, 256>>>(Wp, Wpp);                     // 2
    cvt_wg_kernel<<<(LLAYERS * 3 * HDIM * HDIM) / 256, 256>>>(
        Wih, Whh, Wih_t, Whh_t);                                              // 3
    cudaMemsetAsync(deg, 0, NNODES * sizeof(int));                            // 4
    // h0 = Xp @ Wpp^T + bp      (M=32768, N=256, K=224)
    gemm_tf32_kernel<<<dim3(NNODES / 128, HDIM / 128), 256, GEMM_SMEM>>>(
        Xp, Wpp, bp, h0, FPAD, HDIM, 0);                                      // 5 (captured)
    hist_kernel<<<NEDGES / 256, 256>>>(edst, deg);                            // 6
    scan_kernel<<<1, 1024>>>(deg, rowstart, cursor);
    scatter_kernel<<<NEDGES / 256, 256>>>(edst, cursor, eid);
    cvt_h_kernel<<<(NNODES * HDIM) / 256, 256>>>(h0, ht);

    float* hc = h0;
    float* hn = h1;
    for (int l = 0; l < LLAYERS; l++) {
        prep_wcat_kernel<<<(HDIM * KMSG) / 256, 256>>>(
            Wm + (size_t)l * TTYPES * HDIM * HDIM,
            bm + (size_t)l * TTYPES * HDIM, Wcat);
        aggregate_kernel<<<NNODES, 256>>>(hc, eid, rowstart, esrc, edge_type, S);
        // m = S @ Wcat^T          (N=256, K=2080), output tf32-rounded
        gemm_tf32_kernel<<<dim3(NNODES / 128, HDIM / 128), 256, GEMM_SMEM>>>(
            S, Wcat, (const float*)nullptr, m, KMSG, HDIM, 1);
        // gi = m @ Wih^T + bih ; gh = ht @ Whh^T + bhh   (N=768, K=256)
        gemm_tf32_kernel<<<dim3(NNODES / 128, 3 * HDIM / 128), 256, GEMM_SMEM>>>(
            m, Wih_t + (size_t)l * 3 * HDIM * HDIM, bih + (size_t)l * 3 * HDIM,
            gi, HDIM, 3 * HDIM, 0);
        gemm_tf32_kernel<<<dim3(NNODES / 128, 3 * HDIM / 128), 256, GEMM_SMEM>>>(
            ht, Whh_t + (size_t)l * 3 * HDIM * HDIM, bhh + (size_t)l * 3 * HDIM,
            gh, HDIM, 3 * HDIM, 0);

        gru_kernel<<<(NNODES * HDIM / 4) / 256, 256>>>(gi, gh, hc, hn, ht);
        float* tmp = hc; hc = hn; hn = tmp;
    }

    readout_part_kernel<<<dim3(BGRAPH, 8), 256>>>(hc, part);
    readout_reduce_kernel<<<BGRAPH, HDIM>>>(part, out);
}